// round 2
// baseline (speedup 1.0000x reference)
#include <cuda_runtime.h>

typedef unsigned long long ull;

#define TT       30
#define BB       1048576
#define THREADS  256
#define HALF     (BB / 2)

// Weights in constant memory: uniform-indexed -> LDCU (constant port), off the L1tex path.
__constant__ __align__(16) float cW1[TT * 2 * 20];  // 1200 floats
__constant__ __align__(16) float cB1[TT * 20];      // 600
__constant__ __align__(16) float cW2[TT * 20];      // 600
__constant__ __align__(16) float cB2[TT];           // 30

// ---------------- packed f32x2 helpers ----------------
__device__ __forceinline__ ull pk(float lo, float hi) {
    ull r; asm("mov.b64 %0, {%1,%2};" : "=l"(r) : "f"(lo), "f"(hi)); return r;
}
__device__ __forceinline__ void upk(float& lo, float& hi, ull v) {
    asm("mov.b64 {%0,%1}, %2;" : "=f"(lo), "=f"(hi) : "l"(v));
}
__device__ __forceinline__ ull fma2(ull a, ull b, ull c) {
    ull d; asm("fma.rn.f32x2 %0, %1, %2, %3;" : "=l"(d) : "l"(a), "l"(b), "l"(c)); return d;
}
__device__ __forceinline__ ull add2(ull a, ull b) {
    ull d; asm("add.rn.f32x2 %0, %1, %2;" : "=l"(d) : "l"(a), "l"(b)); return d;
}
__device__ __forceinline__ ull relu2(ull v) {
    float a, b; upk(a, b, v);
    return pk(fmaxf(a, 0.0f), fmaxf(b, 0.0f));
}
// tanh(z) = 1 - 2/(exp(2z)+1), exp via MUFU.EX2, division via MUFU.RCP (~1e-6 rel err)
__device__ __forceinline__ float fast_tanh(float z) {
    float e; asm("ex2.approx.f32 %0, %1;" : "=f"(e) : "f"(z * 2.8853900817779268f));
    float r; asm("rcp.approx.f32 %0, %1;" : "=f"(r) : "f"(e + 1.0f));
    return fmaf(-2.0f, r, 1.0f);
}

// Shared layout (floats): io staging only, 2 regions x 256 elems x 30 floats
#define SMEM_FLOATS (2 * THREADS * TT)   // 15360 floats = 61440 bytes

__global__ __launch_bounds__(THREADS, 3)
void rnn_kernel(const float* __restrict__ gx,
                float* __restrict__ gout)
{
    extern __shared__ float sIO[];

    const int tid = threadIdx.x;
    const int base0 = blockIdx.x * THREADS;  // element base, region 0

    // ---- stage x (coalesced float4: per-region 256*30 floats = 1920 float4) ----
    {
        float4*       d  = (float4*)sIO;
        const float4* s0 = (const float4*)(gx + (size_t)base0 * TT);
        const float4* s1 = (const float4*)(gx + (size_t)(base0 + HALF) * TT);
        for (int i = tid; i < 1920; i += THREADS) d[i]        = s0[i];
        for (int i = tid; i < 1920; i += THREADS) d[1920 + i] = s1[i];
    }
    __syncthreads();

    float* io0 = sIO + tid * TT;                // this thread's element (region 0)
    float* io1 = sIO + (THREADS + tid) * TT;    // this thread's element (region 1)

    const ull* w1u = (const ull*)cW1;   // per t: 20 ulls (10 row0 pairs, 10 row1 pairs)
    const ull* b1u = (const ull*)cB1;   // per t: 10 ulls
    const ull* w2u = (const ull*)cW2;   // per t: 10 ulls

    float o0 = 0.0f, o1 = 0.0f;

    #pragma unroll 1
    for (int t = 0; t < TT; ++t) {
        const ulonglong2* w1t = (const ulonglong2*)(w1u + t * 20);
        const ulonglong2* b1t = (const ulonglong2*)(b1u + t * 10);
        const ulonglong2* w2t = (const ulonglong2*)(w2u + t * 10);
        const float bt2 = cB2[t];
        const float x0  = io0[t];
        const float x1  = io1[t];

        ull xx0 = pk(x0, x0), oo0 = pk(o0, o0);
        ull xx1 = pk(x1, x1), oo1 = pk(o1, o1);
        ull accA0 = pk(bt2, 0.0f), accB0 = pk(0.0f, 0.0f);
        ull accA1 = accA0,         accB1 = accB0;

        #pragma unroll
        for (int q = 0; q < 5; ++q) {
            ulonglong2 wa = w1t[q];       // W1 row0, hidden units 4q..4q+3
            ulonglong2 wb = w1t[5 + q];   // W1 row1, hidden units 4q..4q+3
            ulonglong2 bb = b1t[q];       // b1,      hidden units 4q..4q+3
            ulonglong2 w2 = w2t[q];       // W2,      hidden units 4q..4q+3

            ull hA0 = fma2(xx0, wa.x, fma2(oo0, wb.x, bb.x));
            ull hB0 = fma2(xx0, wa.y, fma2(oo0, wb.y, bb.y));
            ull hA1 = fma2(xx1, wa.x, fma2(oo1, wb.x, bb.x));
            ull hB1 = fma2(xx1, wa.y, fma2(oo1, wb.y, bb.y));

            accA0 = fma2(relu2(hA0), w2.x, accA0);
            accB0 = fma2(relu2(hB0), w2.y, accB0);
            accA1 = fma2(relu2(hA1), w2.x, accA1);
            accB1 = fma2(relu2(hB1), w2.y, accB1);
        }
        {
            float a, b;
            upk(a, b, add2(accA0, accB0));
            o0 = fast_tanh(a + b);
            upk(a, b, add2(accA1, accB1));
            o1 = fast_tanh(a + b);
        }
        io0[t] = o0;    // overwrite consumed x slot with output
        io1[t] = o1;
    }

    __syncthreads();

    // ---- writeback (coalesced float4) ----
    {
        const float4* s  = (const float4*)sIO;
        float4*       d0 = (float4*)(gout + (size_t)base0 * TT);
        float4*       d1 = (float4*)(gout + (size_t)(base0 + HALF) * TT);
        for (int i = tid; i < 1920; i += THREADS) d0[i] = s[i];
        for (int i = tid; i < 1920; i += THREADS) d1[i] = s[1920 + i];
    }
}

extern "C" void kernel_launch(void* const* d_in, const int* in_sizes, int n_in,
                              void* d_out, int out_size)
{
    const float* x  = (const float*)d_in[0];

    // Populate constant bank with D2D async memcpys (graph-capturable, no allocs).
    void *pW1, *pB1, *pW2, *pB2;
    cudaGetSymbolAddress(&pW1, cW1);
    cudaGetSymbolAddress(&pB1, cB1);
    cudaGetSymbolAddress(&pW2, cW2);
    cudaGetSymbolAddress(&pB2, cB2);
    cudaMemcpyAsync(pW1, d_in[1], sizeof(float) * TT * 2 * 20, cudaMemcpyDeviceToDevice);
    cudaMemcpyAsync(pB1, d_in[2], sizeof(float) * TT * 20,     cudaMemcpyDeviceToDevice);
    cudaMemcpyAsync(pW2, d_in[3], sizeof(float) * TT * 20,     cudaMemcpyDeviceToDevice);
    cudaMemcpyAsync(pB2, d_in[4], sizeof(float) * TT,          cudaMemcpyDeviceToDevice);

    const int smem_bytes = SMEM_FLOATS * (int)sizeof(float);  // 61440
    cudaFuncSetAttribute(rnn_kernel, cudaFuncAttributeMaxDynamicSharedMemorySize, smem_bytes);

    rnn_kernel<<<BB / (2 * THREADS), THREADS, smem_bytes>>>(x, (float*)d_out);
}